// round 2
// baseline (speedup 1.0000x reference)
#include <cuda_runtime.h>
#include <cstdint>

// Problem-structure constants (fixed by the model architecture)
#define DD    64     // feature dim per side
#define HID   128    // hidden dim
#define NCLS  5      // classes
#define MAXU  100000
#define MAXM  50000
#define MAXE  1000000

// Scratch: static device globals (allocation-free per harness rules)
__device__ float g_U[(size_t)MAXU * HID];   // 51.2 MB: ufeat @ W1u^T
__device__ float g_I[(size_t)MAXM * HID];   // 25.6 MB: ifeat @ W1i^T + b1
__device__ int   g_src[MAXE];
__device__ int   g_dst[MAXE];
__device__ int   g_is64;

// ---------------------------------------------------------------------------
// Probe: decide whether the index buffers are int64 or int32.
// If int32 data is reinterpreted as int64, high words are other indices
// (virtually never all zero across 2048 probes), so values blow past 200000.
// ---------------------------------------------------------------------------
__global__ void probe_kernel(const unsigned long long* __restrict__ p, int n) {
    __shared__ int bad;
    if (threadIdx.x == 0) bad = 0;
    __syncthreads();
    int m = n * 4 / 8;                 // int64 elements readable if buffer were int32
    int lim = n < 2048 ? n : 2048;
    if (lim > m) lim = m;
    int b = 0;
    for (int i = threadIdx.x; i < lim; i += blockDim.x) {
        unsigned long long v = p[i];
        if (v >= 200000ULL) b = 1;
    }
    if (b) atomicOr(&bad, 1);
    __syncthreads();
    if (threadIdx.x == 0) g_is64 = bad ? 0 : 1;
}

__global__ void convert_kernel(const void* __restrict__ s, const void* __restrict__ d, int E) {
    int i = blockIdx.x * blockDim.x + threadIdx.x;
    if (i >= E) return;
    if (g_is64) {
        g_src[i] = (int)((const long long*)s)[i];
        g_dst[i] = (int)((const long long*)d)[i];
    } else {
        g_src[i] = ((const int*)s)[i];
        g_dst[i] = ((const int*)d)[i];
    }
}

// ---------------------------------------------------------------------------
// Precompute, split per side to stay under the 48KB static smem cap:
//   pre_u: U[u][c] = sum_k ufeat[u][k] * W1[c][k]            (k in [0,64))
//   pre_i: I[m][c] = sum_k ifeat[m][k] * W1[c][64+k] + b1[c]
// Thread = one row. Row features in registers (16 float4). The 32KB W1
// half-tile sits in smem laid out [c][k4] so all lanes of a warp read the
// SAME float4 each step (broadcast LDS.128, conflict-free): 1 LDS / 4 FMA.
// ---------------------------------------------------------------------------
template <int HALF_OFF, bool ADD_B1>
__device__ __forceinline__ void pre_body(const float* __restrict__ feat,
                                         const float* __restrict__ W1,
                                         const float* __restrict__ b1,
                                         float* __restrict__ out_base, int nrows) {
    __shared__ float4 Ws[HID * 16];   // Ws[c*16 + k4] = W1[c][HALF_OFF + k4*4 ..]
    __shared__ float  b1s[HID];

    const float4* W14 = (const float4*)W1;     // W1 row = 32 float4
    for (int i = threadIdx.x; i < HID * 16; i += blockDim.x) {
        int c = i >> 4, k4 = i & 15;
        Ws[i] = W14[c * 32 + HALF_OFF + k4];
    }
    if (ADD_B1)
        for (int i = threadIdx.x; i < HID; i += blockDim.x) b1s[i] = b1[i];
    __syncthreads();

    int row = blockIdx.x * blockDim.x + threadIdx.x;
    if (row >= nrows) return;

    const float4* f4 = (const float4*)(feat + (size_t)row * DD);
    float* out = out_base + (size_t)row * HID;

    float4 f[16];
#pragma unroll
    for (int k = 0; k < 16; k++) f[k] = f4[k];

#pragma unroll
    for (int c0 = 0; c0 < HID; c0 += 4) {
        float4 o;
        float* op = &o.x;
#pragma unroll
        for (int j = 0; j < 4; j++) {
            int c = c0 + j;
            float ax = 0.f, ay = 0.f, az = 0.f, aw = 0.f;
#pragma unroll
            for (int k = 0; k < 16; k++) {
                float4 w = Ws[c * 16 + k];     // warp-uniform address -> broadcast
                ax += f[k].x * w.x;
                ay += f[k].y * w.y;
                az += f[k].z * w.z;
                aw += f[k].w * w.w;
            }
            float r = (ax + ay) + (az + aw);
            if (ADD_B1) r += b1s[c];
            op[j] = r;
        }
        *(float4*)(out + c0) = o;
    }
}

__global__ void pre_u_kernel(const float* __restrict__ ufeat, const float* __restrict__ W1,
                             int nu) {
    pre_body<0, false>(ufeat, W1, nullptr, g_U, nu);
}

__global__ void pre_i_kernel(const float* __restrict__ ifeat, const float* __restrict__ W1,
                             const float* __restrict__ b1, int nm) {
    pre_body<16, true>(ifeat, W1, b1, g_I, nm);
}

// ---------------------------------------------------------------------------
// Edge kernel: 16 lanes per edge (2 edges per warp).
// Lane hl owns h[hl*8 .. hl*8+8): 2 LDG.128 per side cover a 512B row, relu-
// add, 5-class GEMV with W2 held entirely in registers (40 floats/lane),
// 4-step butterfly over the 16-lane half. Grid-stride persistent blocks
// amortize the W2 register fill. L2-bandwidth bound (~1KB gathered/edge;
// U+I = 77MB is L2-resident on B200's ~120MB L2).
// ---------------------------------------------------------------------------
__global__ void __launch_bounds__(256) edge_kernel(const float* __restrict__ W2,
                                                   const float* __restrict__ b2,
                                                   float* __restrict__ out, int E) {
    int lane = threadIdx.x & 31;
    int hl = lane & 15;

    float w[NCLS][8];
#pragma unroll
    for (int c = 0; c < NCLS; c++) {
        float4 a = *(const float4*)(W2 + c * HID + hl * 8);
        float4 b = *(const float4*)(W2 + c * HID + hl * 8 + 4);
        w[c][0] = a.x; w[c][1] = a.y; w[c][2] = a.z; w[c][3] = a.w;
        w[c][4] = b.x; w[c][5] = b.y; w[c][6] = b.z; w[c][7] = b.w;
    }
    float bb = (hl < NCLS) ? b2[hl] : 0.f;

    int groupInBlock = threadIdx.x >> 4;
    int groupsPerBlock = blockDim.x >> 4;
    long gstride = (long)gridDim.x * groupsPerBlock;

    for (long e = (long)blockIdx.x * groupsPerBlock + groupInBlock; e < E; e += gstride) {
        int s = g_src[e];
        int d = g_dst[e];
        const float4* Up = (const float4*)(g_U + (size_t)s * HID) + hl * 2;
        const float4* Ip = (const float4*)(g_I + (size_t)d * HID) + hl * 2;
        float4 u0 = Up[0], u1 = Up[1];
        float4 v0 = Ip[0], v1 = Ip[1];

        float h[8];
        h[0] = fmaxf(u0.x + v0.x, 0.f);
        h[1] = fmaxf(u0.y + v0.y, 0.f);
        h[2] = fmaxf(u0.z + v0.z, 0.f);
        h[3] = fmaxf(u0.w + v0.w, 0.f);
        h[4] = fmaxf(u1.x + v1.x, 0.f);
        h[5] = fmaxf(u1.y + v1.y, 0.f);
        h[6] = fmaxf(u1.z + v1.z, 0.f);
        h[7] = fmaxf(u1.w + v1.w, 0.f);

        float acc[NCLS];
#pragma unroll
        for (int c = 0; c < NCLS; c++) {
            float a0 = h[0] * w[c][0] + h[1] * w[c][1];
            float a1 = h[2] * w[c][2] + h[3] * w[c][3];
            float a2 = h[4] * w[c][4] + h[5] * w[c][5];
            float a3 = h[6] * w[c][6] + h[7] * w[c][7];
            acc[c] = (a0 + a1) + (a2 + a3);
        }

#pragma unroll
        for (int off = 8; off; off >>= 1) {
#pragma unroll
            for (int c = 0; c < NCLS; c++)
                acc[c] += __shfl_xor_sync(0xffffffffu, acc[c], off);
        }

        if (hl < NCLS) {
            float r = (hl == 0) ? acc[0]
                    : (hl == 1) ? acc[1]
                    : (hl == 2) ? acc[2]
                    : (hl == 3) ? acc[3]
                                : acc[4];
            out[e * NCLS + hl] = r + bb;
        }
    }
}

// ---------------------------------------------------------------------------
// Launch: probe -> convert -> pre_u/pre_i -> edge (default stream, capturable)
// Inputs (metadata order): ufeat, ifeat, W1, b1, W2, b2, src_idx, dst_idx
// ---------------------------------------------------------------------------
extern "C" void kernel_launch(void* const* d_in, const int* in_sizes, int n_in,
                              void* d_out, int out_size) {
    const float* ufeat = (const float*)d_in[0];
    const float* ifeat = (const float*)d_in[1];
    const float* W1    = (const float*)d_in[2];
    const float* b1    = (const float*)d_in[3];
    const float* W2    = (const float*)d_in[4];
    const float* b2    = (const float*)d_in[5];
    const void*  src   = d_in[6];
    const void*  dst   = d_in[7];

    int nu = in_sizes[0] / DD;
    int nm = in_sizes[1] / DD;
    int E  = in_sizes[6];

    probe_kernel<<<1, 256>>>((const unsigned long long*)src, E);

    int cgrid = (E + 255) / 256;
    convert_kernel<<<cgrid, 256>>>(src, dst, E);

    pre_u_kernel<<<(nu + 127) / 128, 128>>>(ufeat, W1, nu);
    pre_i_kernel<<<(nm + 127) / 128, 128>>>(ifeat, W1, b1, nm);

    edge_kernel<<<1480, 256>>>(W2, b2, (float*)d_out, E);
}

// round 3
// speedup vs baseline: 1.1697x; 1.1697x over previous
#include <cuda_runtime.h>
#include <cuda_fp16.h>
#include <cstdint>

#define DD    64
#define HID   128
#define NCLS  5
#define MAXU  100000
#define MAXM  50000
#define MAXE  1000000

// Scratch (allocation-free per harness rules). U/I stored as fp16.
__device__ unsigned short g_Uh[(size_t)MAXU * HID];   // 25.6 MB
__device__ unsigned short g_Ih[(size_t)MAXM * HID];   // 12.8 MB
__device__ int g_src[MAXE];
__device__ int g_dst[MAXE];
__device__ int g_is64;

// Packed f32x2 FMA (sm_100): d = a*b + c on two fp32 lanes in one instr.
__device__ __forceinline__ unsigned long long ffma2(unsigned long long a,
                                                    unsigned long long b,
                                                    unsigned long long c) {
    unsigned long long d;
    asm("fma.rn.f32x2 %0, %1, %2, %3;" : "=l"(d) : "l"(a), "l"(b), "l"(c));
    return d;
}
__device__ __forceinline__ float2 u2f(unsigned long long v) {
    float2 r;
    asm("mov.b64 {%0, %1}, %2;" : "=f"(r.x), "=f"(r.y) : "l"(v));
    return r;
}

// XOR swizzle: spread the 8KB-apart column strides of the 4 col-owners of a
// row across distinct 16B words of each 128B bank window.
#define SWZ(off) ((off) ^ (((off) >> 9) & 0x70))

// ---------------------------------------------------------------------------
// Probe int64-vs-int32 index dtype (deterministic; reads only safe range).
// ---------------------------------------------------------------------------
__global__ void probe_kernel(const unsigned long long* __restrict__ p, int n) {
    __shared__ int bad;
    if (threadIdx.x == 0) bad = 0;
    __syncthreads();
    int m = n / 2;                       // u64 elements readable if data were int32
    int lim = n < 2048 ? n : 2048;
    if (lim > m) lim = m;
    int b = 0;
    for (int i = threadIdx.x; i < lim; i += blockDim.x)
        if (p[i] >= 200000ULL) b = 1;
    if (b) atomicOr(&bad, 1);
    __syncthreads();
    if (threadIdx.x == 0) g_is64 = bad ? 0 : 1;
}

__global__ void convert_kernel(const void* __restrict__ s, const void* __restrict__ d, int E) {
    int i = blockIdx.x * blockDim.x + threadIdx.x;
    if (i >= E) return;
    if (g_is64) {
        g_src[i] = (int)((const long long*)s)[i];
        g_dst[i] = (int)((const long long*)d)[i];
    } else {
        g_src[i] = ((const int*)s)[i];
        g_dst[i] = ((const int*)d)[i];
    }
}

// ---------------------------------------------------------------------------
// Merged precompute:
//   U[u][c] = sum_k ufeat[u][k]*W1[c][k]
//   I[m][c] = sum_k ifeat[m][k]*W1[c][64+k] + b1[c]
// 4 threads per row (64 rows / 256-thread block), each owning 32 columns.
// Features held as packed f32x2 pairs in registers; 32KB swizzled W half-tile
// in smem; inner product via fma.rn.f32x2 (pairs over k, no repack movs).
// Results stored fp16, 64B contiguous per thread via 4x STG.128.
// ---------------------------------------------------------------------------
__global__ void __launch_bounds__(256, 2)
pre_kernel(const float* __restrict__ ufeat, const float* __restrict__ ifeat,
           const float* __restrict__ W1, const float* __restrict__ b1,
           int nu, int nm, int blocksU) {
    __shared__ __align__(128) char Wsmem[HID * 256];   // 32KB: 128 cols x 256B
    __shared__ float b1s[HID];

    bool isU = (int)blockIdx.x < blocksU;
    int rowbase = (isU ? blockIdx.x : blockIdx.x - blocksU) * 64;
    int nrows = isU ? nu : nm;
    const float* feat = isU ? ufeat : ifeat;
    unsigned short* outb = isU ? g_Uh : g_Ih;
    int woff = isU ? 0 : 16;                 // float4 offset into a W1 row

    const float4* W14 = (const float4*)W1;   // W1 row = 32 float4
    for (int i = threadIdx.x; i < HID * 16; i += 256) {
        int c = i >> 4, j = i & 15;
        int off = c * 256 + j * 16;
        *(float4*)(Wsmem + SWZ(off)) = W14[c * 32 + woff + j];
    }
    if (!isU)
        for (int i = threadIdx.x; i < HID; i += 256) b1s[i] = b1[i];
    __syncthreads();

    int row = rowbase + (threadIdx.x >> 2);
    if (row >= nrows) return;
    int t4 = threadIdx.x & 3;

    // 64 features = 16 x 16B, each 16B = two packed f32x2 operands.
    ulonglong2 fv[16];
    const ulonglong2* fp = (const ulonglong2*)(feat + (size_t)row * DD);
#pragma unroll
    for (int j = 0; j < 16; j++) fv[j] = fp[j];

    unsigned int res[16];                    // 16 half2 = 32 halves = 64B
#pragma unroll
    for (int cp = 0; cp < 16; cp++) {
        int c0 = t4 * 32 + cp * 2;
        unsigned long long a0x = 0, a0y = 0, a1x = 0, a1y = 0;  // 4 indep chains
        const char* w0b = Wsmem;
#pragma unroll
        for (int j = 0; j < 16; j++) {
            ulonglong2 w0 = *(const ulonglong2*)(w0b + SWZ(c0 * 256 + j * 16));
            ulonglong2 w1 = *(const ulonglong2*)(w0b + SWZ((c0 + 1) * 256 + j * 16));
            a0x = ffma2(fv[j].x, w0.x, a0x);
            a0y = ffma2(fv[j].y, w0.y, a0y);
            a1x = ffma2(fv[j].x, w1.x, a1x);
            a1y = ffma2(fv[j].y, w1.y, a1y);
        }
        float2 p0 = u2f(a0x), q0 = u2f(a0y);
        float2 p1 = u2f(a1x), q1 = u2f(a1y);
        float r0 = (p0.x + p0.y) + (q0.x + q0.y);
        float r1 = (p1.x + p1.y) + (q1.x + q1.y);
        if (!isU) { r0 += b1s[c0]; r1 += b1s[c0 + 1]; }
        __half2 hh = __floats2half2_rn(r0, r1);
        res[cp] = *(unsigned int*)&hh;
    }

    // 64B contiguous store per thread (4 x 16B); warp covers full rows.
    uint4* o4 = (uint4*)(outb + (size_t)row * HID + t4 * 32);
#pragma unroll
    for (int q = 0; q < 4; q++)
        o4[q] = make_uint4(res[q * 4], res[q * 4 + 1], res[q * 4 + 2], res[q * 4 + 3]);
}

// ---------------------------------------------------------------------------
// Edge kernel: 16 lanes per edge (2 edges/warp). Lane hl loads 16B (8 fp16)
// of U and of I, relu-add in half2, fp32 5-class GEMV with W2 entirely in
// registers, 4-step butterfly. ~540B/edge touched; U/I (38MB) L2-resident.
// ---------------------------------------------------------------------------
__global__ void __launch_bounds__(256) edge_kernel(const float* __restrict__ W2,
                                                   const float* __restrict__ b2,
                                                   float* __restrict__ out, int E) {
    int lane = threadIdx.x & 31;
    int hl = lane & 15;

    float w[NCLS][8];
#pragma unroll
    for (int c = 0; c < NCLS; c++) {
        float4 a = *(const float4*)(W2 + c * HID + hl * 8);
        float4 b = *(const float4*)(W2 + c * HID + hl * 8 + 4);
        w[c][0] = a.x; w[c][1] = a.y; w[c][2] = a.z; w[c][3] = a.w;
        w[c][4] = b.x; w[c][5] = b.y; w[c][6] = b.z; w[c][7] = b.w;
    }
    float bb = (hl < NCLS) ? b2[hl] : 0.f;
    __half2 z2 = __float2half2_rn(0.f);

    int groupInBlock = threadIdx.x >> 4;
    int groupsPerBlock = blockDim.x >> 4;
    long gstride = (long)gridDim.x * groupsPerBlock;

    for (long e = (long)blockIdx.x * groupsPerBlock + groupInBlock; e < E; e += gstride) {
        int s = g_src[e];
        int d = g_dst[e];
        uint4 uu = *((const uint4*)(g_Uh + (size_t)s * HID) + hl);
        uint4 vv = *((const uint4*)(g_Ih + (size_t)d * HID) + hl);
        const __half2* u2 = (const __half2*)&uu;
        const __half2* v2 = (const __half2*)&vv;

        float h[8];
#pragma unroll
        for (int j = 0; j < 4; j++) {
            __half2 hv = __hmax2(__hadd2(u2[j], v2[j]), z2);
            float2 f = __half22float2(hv);
            h[2 * j] = f.x;
            h[2 * j + 1] = f.y;
        }

        float acc[NCLS];
#pragma unroll
        for (int c = 0; c < NCLS; c++) {
            float a0 = h[0] * w[c][0] + h[1] * w[c][1];
            float a1 = h[2] * w[c][2] + h[3] * w[c][3];
            float a2 = h[4] * w[c][4] + h[5] * w[c][5];
            float a3 = h[6] * w[c][6] + h[7] * w[c][7];
            acc[c] = (a0 + a1) + (a2 + a3);
        }

#pragma unroll
        for (int off = 8; off; off >>= 1) {
#pragma unroll
            for (int c = 0; c < NCLS; c++)
                acc[c] += __shfl_xor_sync(0xffffffffu, acc[c], off);
        }

        if (hl < NCLS) {
            float r = (hl == 0) ? acc[0]
                    : (hl == 1) ? acc[1]
                    : (hl == 2) ? acc[2]
                    : (hl == 3) ? acc[3]
                                : acc[4];
            out[e * NCLS + hl] = r + bb;
        }
    }
}

// ---------------------------------------------------------------------------
// Inputs (metadata order): ufeat, ifeat, W1, b1, W2, b2, src_idx, dst_idx
// ---------------------------------------------------------------------------
extern "C" void kernel_launch(void* const* d_in, const int* in_sizes, int n_in,
                              void* d_out, int out_size) {
    const float* ufeat = (const float*)d_in[0];
    const float* ifeat = (const float*)d_in[1];
    const float* W1    = (const float*)d_in[2];
    const float* b1    = (const float*)d_in[3];
    const float* W2    = (const float*)d_in[4];
    const float* b2    = (const float*)d_in[5];
    const void*  src   = d_in[6];
    const void*  dst   = d_in[7];

    int nu = in_sizes[0] / DD;
    int nm = in_sizes[1] / DD;
    int E  = in_sizes[6];

    probe_kernel<<<1, 256>>>((const unsigned long long*)src, E);
    convert_kernel<<<(E + 255) / 256, 256>>>(src, dst, E);

    int blocksU = (nu + 63) / 64;
    int blocksI = (nm + 63) / 64;
    pre_kernel<<<blocksU + blocksI, 256>>>(ufeat, ifeat, W1, b1, nu, nm, blocksU);

    edge_kernel<<<1480, 256>>>(W2, b2, (float*)d_out, E);
}

// round 4
// speedup vs baseline: 2.1017x; 1.7967x over previous
#include <cuda_runtime.h>
#include <cuda_fp16.h>

#define DD    64
#define HID   128
#define NCLS  5
#define MAXU  100000
#define MAXM  50000
#define MAXE  1000000

// Scratch (allocation-free per harness rules). U/I stored as fp16.
__device__ unsigned short g_Uh[(size_t)MAXU * HID];   // 25.6 MB
__device__ unsigned short g_Ih[(size_t)MAXM * HID];   // 12.8 MB
__device__ int g_src[MAXE];
__device__ int g_dst[MAXE];
__device__ int g_is64;

// ---- packed f32x2 helpers (sm_100) ----
__device__ __forceinline__ unsigned long long ffma2(unsigned long long a,
                                                    unsigned long long b,
                                                    unsigned long long c) {
    unsigned long long d;
    asm("fma.rn.f32x2 %0, %1, %2, %3;" : "=l"(d) : "l"(a), "l"(b), "l"(c));
    return d;
}
__device__ __forceinline__ float2 u2f(unsigned long long v) {
    float2 r;
    asm("mov.b64 {%0, %1}, %2;" : "=f"(r.x), "=f"(r.y) : "l"(v));
    return r;
}
__device__ __forceinline__ unsigned long long pack2(float x, float y) {
    unsigned long long r;
    asm("mov.b64 %0, {%1, %2};" : "=l"(r) : "f"(x), "f"(y));
    return r;
}

// ---------------------------------------------------------------------------
// Probe int64-vs-int32 index dtype (deterministic; reads only safe range).
// ---------------------------------------------------------------------------
__global__ void probe_kernel(const unsigned long long* __restrict__ p, int n) {
    __shared__ int bad;
    if (threadIdx.x == 0) bad = 0;
    __syncthreads();
    int m = n / 2;
    int lim = n < 2048 ? n : 2048;
    if (lim > m) lim = m;
    int b = 0;
    for (int i = threadIdx.x; i < lim; i += blockDim.x)
        if (p[i] >= 200000ULL) b = 1;
    if (b) atomicOr(&bad, 1);
    __syncthreads();
    if (threadIdx.x == 0) g_is64 = bad ? 0 : 1;
}

__global__ void convert_kernel(const void* __restrict__ s, const void* __restrict__ d, int E) {
    int i = blockIdx.x * blockDim.x + threadIdx.x;
    if (i >= E) return;
    if (g_is64) {
        g_src[i] = (int)((const long long*)s)[i];
        g_dst[i] = (int)((const long long*)d)[i];
    } else {
        g_src[i] = ((const int*)s)[i];
        g_dst[i] = ((const int*)d)[i];
    }
}

// ---------------------------------------------------------------------------
// Pre v2: register-tiled GEMM.  Block = 256 threads as 16(tr) x 16(tc),
// thread tile = 8 rows x 8 cols, block tile = 128 rows x 128 cols, k=64
// processed in 2 halves of 32 (two 16KB smem tiles, transposed to [k][*]).
// FFMA2 packed over ROW PAIRS: acc[rp][c].x|.y are rows 2rp|2rp+1 results,
// so no horizontal reduction. Smem reads = 8KB/row (was 32KB/row).
// ---------------------------------------------------------------------------
__global__ void __launch_bounds__(256, 2)
pre2_kernel(const float* __restrict__ ufeat, const float* __restrict__ ifeat,
            const float* __restrict__ W1, const float* __restrict__ b1,
            int nu, int nm, int blocksU) {
    __shared__ __align__(16) float Fs[32 * 128];   // 16KB [k][row]
    __shared__ __align__(16) float Wt[32 * 128];   // 16KB [k][col]

    bool isU = (int)blockIdx.x < blocksU;
    int rowbase = (isU ? blockIdx.x : blockIdx.x - blocksU) * 128;
    int nrows = isU ? nu : nm;
    const float4* F4 = (const float4*)(isU ? ufeat : ifeat);   // row = 16 float4
    const float4* W14 = (const float4*)W1;                     // row = 32 float4
    int woff = isU ? 0 : 16;
    unsigned short* outb = isU ? g_Uh : g_Ih;

    int tid = threadIdx.x;
    int tr = tid >> 4, tc = tid & 15;
    int r0 = tr * 8, c0 = tc * 8;

    unsigned long long acc[4][8];
#pragma unroll
    for (int a = 0; a < 4; a++)
#pragma unroll
        for (int j = 0; j < 8; j++) acc[a][j] = 0ULL;

#pragma unroll
    for (int h = 0; h < 2; h++) {
        if (h) __syncthreads();
        // Fill both tiles transposed. 1024 float4 each; coalesced gmem reads,
        // conflict-free STS.32 (lanes hit consecutive r for fixed k).
#pragma unroll
        for (int it = 0; it < 4; it++) {
            int idx = it * 256 + tid;        // 0..1023
            int r = idx >> 3;                // 0..127 (row or col)
            int f = idx & 7;                 // float4 within k-half
            int rr = rowbase + r;
            if (rr >= nrows) rr = nrows - 1; // clamp (block always has >=1 row)
            float4 v = F4[(size_t)rr * 16 + h * 8 + f];
            Fs[(f * 4 + 0) * 128 + r] = v.x;
            Fs[(f * 4 + 1) * 128 + r] = v.y;
            Fs[(f * 4 + 2) * 128 + r] = v.z;
            Fs[(f * 4 + 3) * 128 + r] = v.w;
            float4 u = W14[(size_t)r * 32 + woff + h * 8 + f];
            Wt[(f * 4 + 0) * 128 + r] = u.x;
            Wt[(f * 4 + 1) * 128 + r] = u.y;
            Wt[(f * 4 + 2) * 128 + r] = u.z;
            Wt[(f * 4 + 3) * 128 + r] = u.w;
        }
        __syncthreads();

#pragma unroll 4
        for (int k = 0; k < 32; k++) {
            // 8 row-features as 4 packed pairs (8B-aligned: r0 multiple of 8)
            const unsigned long long* frow =
                (const unsigned long long*)&Fs[k * 128 + r0];
            unsigned long long f2[4];
            f2[0] = frow[0]; f2[1] = frow[1]; f2[2] = frow[2]; f2[3] = frow[3];
            float4 wa = *(const float4*)&Wt[k * 128 + c0];
            float4 wb = *(const float4*)&Wt[k * 128 + c0 + 4];
            unsigned long long wd[8];
            wd[0] = pack2(wa.x, wa.x); wd[1] = pack2(wa.y, wa.y);
            wd[2] = pack2(wa.z, wa.z); wd[3] = pack2(wa.w, wa.w);
            wd[4] = pack2(wb.x, wb.x); wd[5] = pack2(wb.y, wb.y);
            wd[6] = pack2(wb.z, wb.z); wd[7] = pack2(wb.w, wb.w);
#pragma unroll
            for (int rp = 0; rp < 4; rp++)
#pragma unroll
                for (int j = 0; j < 8; j++)
                    acc[rp][j] = ffma2(f2[rp], wd[j], acc[rp][j]);
        }
    }

    float bv[8];
#pragma unroll
    for (int j = 0; j < 8; j++) bv[j] = 0.f;
    if (!isU) {
#pragma unroll
        for (int j = 0; j < 8; j++) bv[j] = b1[c0 + j];
    }

    // Store: each row pair -> two 16B fp16 stores (8 halves each).
#pragma unroll
    for (int rp = 0; rp < 4; rp++) {
        float x[8], y[8];
#pragma unroll
        for (int j = 0; j < 8; j++) {
            float2 t = u2f(acc[rp][j]);
            x[j] = t.x + bv[j];
            y[j] = t.y + bv[j];
        }
        int rowA = rowbase + r0 + rp * 2;
        int rowB = rowA + 1;
        if (rowA < nrows) {
            __half2 h0 = __floats2half2_rn(x[0], x[1]);
            __half2 h1 = __floats2half2_rn(x[2], x[3]);
            __half2 h2 = __floats2half2_rn(x[4], x[5]);
            __half2 h3 = __floats2half2_rn(x[6], x[7]);
            uint4 o = make_uint4(*(unsigned*)&h0, *(unsigned*)&h1,
                                 *(unsigned*)&h2, *(unsigned*)&h3);
            *(uint4*)(outb + (size_t)rowA * HID + c0) = o;
        }
        if (rowB < nrows) {
            __half2 h0 = __floats2half2_rn(y[0], y[1]);
            __half2 h1 = __floats2half2_rn(y[2], y[3]);
            __half2 h2 = __floats2half2_rn(y[4], y[5]);
            __half2 h3 = __floats2half2_rn(y[6], y[7]);
            uint4 o = make_uint4(*(unsigned*)&h0, *(unsigned*)&h1,
                                 *(unsigned*)&h2, *(unsigned*)&h3);
            *(uint4*)(outb + (size_t)rowB * HID + c0) = o;
        }
    }
}

// ---------------------------------------------------------------------------
// Edge v2: 8 lanes per edge (4 edges/warp). Lane hl owns h[hl*16..+16):
// 2 LDG.128 per side, relu-add in half2, packed-FFMA2 5-class GEMV with W2
// in registers (40 pairs/lane), 3-step butterfly over the 8-lane group.
// Persistent grid-stride loop with idx prefetch. E%4==0 keeps warps uniform.
// ---------------------------------------------------------------------------
__global__ void __launch_bounds__(128) edge2_kernel(const float* __restrict__ W2,
                                                    const float* __restrict__ b2,
                                                    float* __restrict__ out, long E) {
    int lane = threadIdx.x & 31;
    int g = lane >> 3;
    int hl = lane & 7;

    unsigned long long w2[NCLS][8];
#pragma unroll
    for (int c = 0; c < NCLS; c++) {
        const float4* p = (const float4*)(W2 + c * HID + hl * 16);
        float4 a = p[0], b = p[1], cc = p[2], d = p[3];
        w2[c][0] = pack2(a.x, a.y);  w2[c][1] = pack2(a.z, a.w);
        w2[c][2] = pack2(b.x, b.y);  w2[c][3] = pack2(b.z, b.w);
        w2[c][4] = pack2(cc.x, cc.y); w2[c][5] = pack2(cc.z, cc.w);
        w2[c][6] = pack2(d.x, d.y);  w2[c][7] = pack2(d.z, d.w);
    }
    float bb = (hl < NCLS) ? b2[hl] : 0.f;
    __half2 z2 = __float2half2_rn(0.f);

    long warpId = (long)blockIdx.x * (blockDim.x >> 5) + (threadIdx.x >> 5);
    long stride4 = (long)gridDim.x * (blockDim.x >> 5) * 4;
    long e = warpId * 4 + g;
    if (e >= E) return;                          // warp-uniform (E % 4 == 0)

    int s = g_src[e], dI = g_dst[e];
    while (true) {
        long en = e + stride4;
        int sn = 0, dn = 0;
        bool more = (en < E);                    // warp-uniform
        if (more) { sn = g_src[en]; dn = g_dst[en]; }

        const uint4* Up = (const uint4*)g_Uh + (size_t)s * 16 + hl * 2;
        const uint4* Ip = (const uint4*)g_Ih + (size_t)dI * 16 + hl * 2;
        uint4 u0 = Up[0], u1 = Up[1];
        uint4 v0 = Ip[0], v1 = Ip[1];

        unsigned long long h2[8];
        {
            const __half2* ua = (const __half2*)&u0;
            const __half2* va = (const __half2*)&v0;
            const __half2* ub = (const __half2*)&u1;
            const __half2* vb = (const __half2*)&v1;
#pragma unroll
            for (int j = 0; j < 4; j++) {
                __half2 hv = __hmax2(__hadd2(ua[j], va[j]), z2);
                float2 f = __half22float2(hv);
                h2[j] = pack2(f.x, f.y);
            }
#pragma unroll
            for (int j = 0; j < 4; j++) {
                __half2 hv = __hmax2(__hadd2(ub[j], vb[j]), z2);
                float2 f = __half22float2(hv);
                h2[4 + j] = pack2(f.x, f.y);
            }
        }

        float acc[NCLS];
#pragma unroll
        for (int c = 0; c < NCLS; c++) {
            unsigned long long a2 = 0ULL;
#pragma unroll
            for (int j = 0; j < 8; j++)
                a2 = ffma2(h2[j], w2[c][j], a2);
            float2 t = u2f(a2);
            acc[c] = t.x + t.y;
        }

#pragma unroll
        for (int off = 4; off; off >>= 1) {
#pragma unroll
            for (int c = 0; c < NCLS; c++)
                acc[c] += __shfl_xor_sync(0xffffffffu, acc[c], off);
        }

        if (hl < NCLS) {
            float r = (hl == 0) ? acc[0]
                    : (hl == 1) ? acc[1]
                    : (hl == 2) ? acc[2]
                    : (hl == 3) ? acc[3]
                                : acc[4];
            out[e * NCLS + hl] = r + bb;
        }

        if (!more) break;
        e = en; s = sn; dI = dn;
    }
}

// ---------------------------------------------------------------------------
// Inputs (metadata order): ufeat, ifeat, W1, b1, W2, b2, src_idx, dst_idx
// ---------------------------------------------------------------------------
extern "C" void kernel_launch(void* const* d_in, const int* in_sizes, int n_in,
                              void* d_out, int out_size) {
    const float* ufeat = (const float*)d_in[0];
    const float* ifeat = (const float*)d_in[1];
    const float* W1    = (const float*)d_in[2];
    const float* b1    = (const float*)d_in[3];
    const float* W2    = (const float*)d_in[4];
    const float* b2    = (const float*)d_in[5];
    const void*  src   = d_in[6];
    const void*  dst   = d_in[7];

    int nu = in_sizes[0] / DD;
    int nm = in_sizes[1] / DD;
    int E  = in_sizes[6];

    probe_kernel<<<1, 256>>>((const unsigned long long*)src, E);
    convert_kernel<<<(E + 255) / 256, 256>>>(src, dst, E);

    int blocksU = (nu + 127) / 128;
    int blocksI = (nm + 127) / 128;
    pre2_kernel<<<blocksU + blocksI, 256>>>(ufeat, ifeat, W1, b1, nu, nm, blocksU);

    edge2_kernel<<<444, 128>>>(W2, b2, (float*)d_out, (long)E);
}